// round 9
// baseline (speedup 1.0000x reference)
#include <cuda_runtime.h>
#include <cuda_fp16.h>
#include <cstdint>

// ConvLSTM2D via mma.sync fp16 (baseline PTX) with fp16 x2 3-product split.
//   g_xs: 96 ch  = [xh | xh | xl],  weights B' = [Wh | Wl | Wh]
//   g_hs: 192 ch = [hh | hh | hl],  weights B' = [Uh | Ul | Uh]
// h-state ping-pong buffered (halo race fix, round 7).
// Round 8: Kc=128 slabs (21 vs 41) to amortize per-slab barrier/wait overhead.

#define kT    16
#define kNPix 32768
#define KX3   896        // x K-part: 9*96=864, padded to 896 (=7*128)
#define KALL3 2688       // 896 + 9*192(=1728 padded to 1792)
#define NS_ALL 21
#define NS_X   7

// -------- device scratch (allocation-free rule) -----------------------------
__device__ __half g_xs[(size_t)8 * 16 * 4096 * 96];      // 100.7 MB
__device__ __half g_hs[2][(size_t)kNPix * 192];          // 2 x 12.6 MB
__device__ float  g_c [(size_t)kNPix * 64];              // 8.4 MB
__device__ __half g_Wb[(size_t)256 * KALL3];             // 1.38 MB
__device__ __align__(16) __half g_zeros[8];              // stays zero

// -------- helpers -----------------------------------------------------------
__device__ __forceinline__ uint32_t sm_u32(const void* p) {
    return (uint32_t)__cvta_generic_to_shared(p);
}
__device__ __forceinline__ uint32_t swz(uint32_t o) { return o ^ ((o >> 3) & 0x70); }

__device__ __forceinline__ void cp16(uint32_t dst, const void* src) {
    asm volatile("cp.async.cg.shared.global [%0], [%1], 16;"
                 :: "r"(dst), "l"(src));
}
__device__ __forceinline__ void cp_commit() {
    asm volatile("cp.async.commit_group;" ::: "memory");
}
__device__ __forceinline__ void cp_wait0() {
    asm volatile("cp.async.wait_group 0;" ::: "memory");
}
__device__ __forceinline__ void ldsm4(uint32_t* r, uint32_t a) {
    asm volatile("ldmatrix.sync.aligned.m8n8.x4.shared.b16 {%0,%1,%2,%3}, [%4];"
                 : "=r"(r[0]), "=r"(r[1]), "=r"(r[2]), "=r"(r[3]) : "r"(a));
}
__device__ __forceinline__ void mma16816(float* c, const uint32_t* a,
                                         const uint32_t* b) {
    asm volatile(
        "mma.sync.aligned.m16n8k16.row.col.f32.f16.f16.f32 "
        "{%0,%1,%2,%3}, {%4,%5,%6,%7}, {%8,%9}, {%0,%1,%2,%3};"
        : "+f"(c[0]), "+f"(c[1]), "+f"(c[2]), "+f"(c[3])
        : "r"(a[0]), "r"(a[1]), "r"(a[2]), "r"(a[3]), "r"(b[0]), "r"(b[1]));
}
__device__ __forceinline__ float hsig(float v) {
    return fminf(fmaxf(v + 3.f, 0.f), 6.f) * (1.f / 6.f);
}

// -------- precompute: B' weights in interleaved K order ----------------------
__global__ void wb_kernel(const float* __restrict__ W, const float* __restrict__ U)
{
    int k_all = blockIdx.x;      // 0..KALL3-1
    int n = threadIdx.x;         // 0..255
    float v = 0.f;
    int sub = 0;
    bool valid = false;
    if (k_all < KX3) {
        if (k_all < 864) {
            int tap = k_all / 96, r = k_all % 96;
            sub = r / 32;
            int cin = r % 32;
            v = W[(size_t)(tap * 32 + cin) * 256 + n];
            valid = true;
        }
    } else {
        int k = k_all - KX3;
        if (k < 1728) {
            int tap = k / 192, r = k % 192;
            sub = r / 64;
            int cin = r % 64;
            v = U[(size_t)(tap * 64 + cin) * 256 + n];
            valid = true;
        }
    }
    __half o = __float2half(0.f);
    if (valid) {
        __half hi = __float2half(v);
        o = (sub == 1) ? __float2half(v - __half2float(hi)) : hi;
    }
    g_Wb[(size_t)n * KALL3 + k_all] = o;
}

// -------- precompute: x split image ------------------------------------------
__global__ void xs_kernel(const float* __restrict__ x)
{
    size_t i = (size_t)blockIdx.x * blockDim.x + threadIdx.x;  // 16.7M
    int cin = (int)(i & 31);
    size_t p = i >> 5;
    float v = x[i];
    __half hi = __float2half(v);
    __half lo = __float2half(v - __half2float(hi));
    g_xs[p * 96 + cin]      = hi;
    g_xs[p * 96 + 32 + cin] = hi;
    g_xs[p * 96 + 64 + cin] = lo;
}

// -------- main step kernel ---------------------------------------------------
// 256 CTAs x 512 threads; CTA = 128 pixels x 256 gates; 16 warps = 4(M)x4(N),
// warp tile 32x64. Kc=128 stored as two 64-k subtiles (SW128 each).
// Dynamic smem: A[2] 32KB @0/32K, B[2] 64KB @64K/128K  -> 192KB.

__global__ __launch_bounds__(512, 1)
void lstm_step_kernel(const float* __restrict__ bias, float* __restrict__ out,
                      int t, int last)
{
    extern __shared__ __align__(16) char dsm_raw[];
    __shared__ float s_bias[256];

    const int tid = threadIdx.x;
    const int wid = tid >> 5;
    const int lane = tid & 31;
    const int m_tile = blockIdx.x * 128;

    const uint32_t dyn = sm_u32(dsm_raw);
    const uint32_t base = (dyn + 1023) & ~1023u;
    char* dptr = dsm_raw + (base - dyn);

    if (tid < 64) ((float4*)s_bias)[tid] = ((const float4*)bias)[tid];

    const int NS = (t == 0) ? NS_X : NS_ALL;
    const __half* h_rd = g_hs[t & 1];          // h_{t-1}
    __half*       h_wr = g_hs[(t & 1) ^ 1];    // h_t

    auto load_slab = [&](int s, int buf) {
        const uint32_t abuf = base + buf * 32768;
        const uint32_t bbuf = base + 65536 + buf * 65536;
        // A: 2048 16B chunks (128 rows x 16 kgroups), 4 per thread
#pragma unroll
        for (int i = 0; i < 4; i++) {
            int c = tid + i * 512;
            int m = c >> 4, kg = c & 15;
            int k0 = s * 128 + kg * 8;
            int p = m_tile + m;
            int bb = p >> 12, rem = p & 4095, py = rem >> 6, px = rem & 63;
            const __half* src = g_zeros;
            if (k0 < KX3) {
                if (k0 < 864) {
                    int tap = k0 / 96, ch = k0 % 96;   // ch multiple of 8
                    int y = py + tap / 3 - 1, xw = px + tap % 3 - 1;
                    if ((unsigned)y < 64u && (unsigned)xw < 64u)
                        src = g_xs + ((size_t)((bb * 16 + t) * 4096
                                               + (y << 6) + xw)) * 96 + ch;
                }
            } else {
                int k = k0 - KX3;
                if (k < 1728) {
                    int tap = k / 192, ch = k % 192;    // ch multiple of 8
                    int y = py + tap / 3 - 1, xw = px + tap % 3 - 1;
                    if ((unsigned)y < 64u && (unsigned)xw < 64u)
                        src = h_rd + ((size_t)((bb << 12) + (y << 6) + xw)) * 192 + ch;
                }
            }
            cp16(abuf + (uint32_t)(kg >> 3) * 16384
                      + swz((uint32_t)(m * 128 + (kg & 7) * 16)), src);
        }
        // B: 4096 16B chunks (256 rows x 16 kgroups), 8 per thread
#pragma unroll
        for (int i = 0; i < 8; i++) {
            int c = tid + i * 512;
            int n = c >> 4, kg = c & 15;
            cp16(bbuf + (uint32_t)(kg >> 3) * 32768
                      + swz((uint32_t)(n * 128 + (kg & 7) * 16)),
                 g_Wb + (size_t)n * KALL3 + s * 128 + kg * 8);
        }
    };

    // accumulators: 2 m-subtiles x 8 n-subtiles x 4 f32
    float cfr[2][8][4];
#pragma unroll
    for (int i = 0; i < 2; i++)
#pragma unroll
        for (int j = 0; j < 8; j++)
#pragma unroll
            for (int q = 0; q < 4; q++) cfr[i][j][q] = 0.f;

    const int wm0 = (wid >> 2) * 32;
    const int wn0 = (wid & 3) * 64;

    load_slab(0, 0);
    cp_commit();

    for (int s = 0; s < NS; s++) {
        const int cur = s & 1;
        cp_wait0();
        __syncthreads();
        if (s + 1 < NS) { load_slab(s + 1, cur ^ 1); cp_commit(); }

        const uint32_t abuf = base + cur * 32768;
        const uint32_t bbuf = base + 65536 + cur * 65536;
        const uint32_t arow = (uint32_t)(wm0 + (lane & 7) + ((lane >> 3) & 1) * 8);
        const uint32_t brow = (uint32_t)(wn0 + (lane & 7) + (lane >> 4) * 8);
#pragma unroll
        for (int ks = 0; ks < 8; ks++) {
            const uint32_t asub = abuf + (uint32_t)(ks >> 2) * 16384;
            const uint32_t bsub = bbuf + (uint32_t)(ks >> 2) * 32768;
            const uint32_t acol = (uint32_t)((ks & 3) * 16 + (lane >> 4) * 8) * 2;
            const uint32_t bcol = (uint32_t)((ks & 3) * 16 + ((lane >> 3) & 1) * 8) * 2;
            uint32_t a0[4], a1[4];
            ldsm4(a0, asub + swz(arow * 128 + acol));
            ldsm4(a1, asub + swz((arow + 16) * 128 + acol));
#pragma unroll
            for (int p = 0; p < 4; p++) {
                uint32_t b[4];
                ldsm4(b, bsub + swz((brow + p * 16) * 128 + bcol));
                mma16816(cfr[0][2 * p],     a0, b);
                mma16816(cfr[0][2 * p + 1], a0, b + 2);
                mma16816(cfr[1][2 * p],     a1, b);
                mma16816(cfr[1][2 * p + 1], a1, b + 2);
            }
        }
    }
    __syncthreads();   // all mma done; smem buffers free for staging

    // ---- fused LSTM epilogue: two rounds of 64 pixels x 256 gates ----------
    float* zbuf = (float*)dptr;                 // 64*256 f32 = 64KB (A region)

    for (int r = 0; r < 2; r++) {
        if ((wm0 >> 6) == r) {
#pragma unroll
            for (int mi = 0; mi < 2; mi++) {
                int ml = (wm0 & 63) + mi * 16 + (lane >> 2);
#pragma unroll
                for (int nj = 0; nj < 8; nj++) {
                    int n = wn0 + nj * 8 + 2 * (lane & 3);
                    *(float2*)(zbuf + ml * 256 + n) =
                        make_float2(cfr[mi][nj][0], cfr[mi][nj][1]);
                    *(float2*)(zbuf + (ml + 8) * 256 + n) =
                        make_float2(cfr[mi][nj][2], cfr[mi][nj][3]);
                }
            }
        }
        __syncthreads();

        {   // gates: 64 pixels x 64 f; thread -> pixel p, 8 f values
            const int p = tid >> 3;
            const int f0 = (tid & 7) * 8;
            const int pix = m_tile + r * 64 + p;
            const float* zr = zbuf + p * 256;
            float cp8[8] = {0.f, 0.f, 0.f, 0.f, 0.f, 0.f, 0.f, 0.f};
            if (t > 0) {
                float4 c0 = *(const float4*)(g_c + (size_t)pix * 64 + f0);
                float4 c1 = *(const float4*)(g_c + (size_t)pix * 64 + f0 + 4);
                cp8[0] = c0.x; cp8[1] = c0.y; cp8[2] = c0.z; cp8[3] = c0.w;
                cp8[4] = c1.x; cp8[5] = c1.y; cp8[6] = c1.z; cp8[7] = c1.w;
            }
            float cn8[8], hn8[8];
#pragma unroll
            for (int j = 0; j < 8; j++) {
                int f = f0 + j;
                float vi = zr[f]       + s_bias[f];
                float vf = zr[64 + f]  + s_bias[64 + f];
                float vc = zr[128 + f] + s_bias[128 + f];
                float vo = zr[192 + f] + s_bias[192 + f];
                float cn = hsig(vf) * cp8[j] + hsig(vi) * fmaxf(vc, 0.f);
                cn8[j] = cn;
                hn8[j] = hsig(vo) * fmaxf(cn, 0.f);
            }
            if (last) {
                *(float4*)(out + (size_t)pix * 64 + f0) =
                    make_float4(hn8[0], hn8[1], hn8[2], hn8[3]);
                *(float4*)(out + (size_t)pix * 64 + f0 + 4) =
                    make_float4(hn8[4], hn8[5], hn8[6], hn8[7]);
            } else {
                *(float4*)(g_c + (size_t)pix * 64 + f0) =
                    make_float4(cn8[0], cn8[1], cn8[2], cn8[3]);
                *(float4*)(g_c + (size_t)pix * 64 + f0 + 4) =
                    make_float4(cn8[4], cn8[5], cn8[6], cn8[7]);
                // pack hi/lo splits in registers
                uint32_t ph[4], pl[4];
#pragma unroll
                for (int j2 = 0; j2 < 4; j2++) {
                    __half h0 = __float2half(hn8[2 * j2]);
                    __half h1 = __float2half(hn8[2 * j2 + 1]);
                    __half l0 = __float2half(hn8[2 * j2]     - __half2float(h0));
                    __half l1 = __float2half(hn8[2 * j2 + 1] - __half2float(h1));
                    ph[j2] = (uint32_t)__half_as_ushort(h0)
                           | ((uint32_t)__half_as_ushort(h1) << 16);
                    pl[j2] = (uint32_t)__half_as_ushort(l0)
                           | ((uint32_t)__half_as_ushort(l1) << 16);
                }
                uint4 vh = make_uint4(ph[0], ph[1], ph[2], ph[3]);
                uint4 vl = make_uint4(pl[0], pl[1], pl[2], pl[3]);
                *(uint4*)(h_wr + (size_t)pix * 192 + f0)       = vh;
                *(uint4*)(h_wr + (size_t)pix * 192 + 64 + f0)  = vh;
                *(uint4*)(h_wr + (size_t)pix * 192 + 128 + f0) = vl;
            }
        }
        __syncthreads();
    }
}

// ---------------------------------------------------------------------------

extern "C" void kernel_launch(void* const* d_in, const int* in_sizes, int n_in,
                              void* d_out, int out_size)
{
    const float* x    = (const float*)d_in[0];   // (8,16,64,64,32)
    const float* Wp   = (const float*)d_in[1];   // (3,3,32,256)
    const float* Up   = (const float*)d_in[2];   // (3,3,64,256)
    const float* bias = (const float*)d_in[3];   // (256,)
    float* out = (float*)d_out;                  // (8,64,64,64)

    cudaFuncSetAttribute(lstm_step_kernel,
                         cudaFuncAttributeMaxDynamicSharedMemorySize, 197632);

    wb_kernel<<<KALL3, 256>>>(Wp, Up);
    xs_kernel<<<65536, 256>>>(x);

    for (int t = 0; t < kT; t++)
        lstm_step_kernel<<<256, 512, 197632>>>(bias, out, t, t == kT - 1 ? 1 : 0);
}

// round 10
// speedup vs baseline: 1.2232x; 1.2232x over previous
#include <cuda_runtime.h>
#include <cuda_fp16.h>
#include <cstdint>

// ConvLSTM2D via mma.sync fp16 (baseline PTX) with fp16 x2 3-product split.
//   g_xs: 96 ch  = [xh | xh | xl],  weights B' = [Wh | Wl | Wh]
//   g_hs: 192 ch = [hh | hh | hl],  weights B' = [Uh | Ul | Uh]
// h-state ping-pong buffered (halo race fix, round 7).
// Round 10: back to Kc=64 (round-8 Kc=128 regressed) + 3-stage cp.async ring
// (wait_group 1) so each slab load gets ~2 slabs of compute time to land.

#define kT    16
#define kNPix 32768
#define KX2   896        // x K-part: 9*96=864, padded to 896
#define KALL2 2624       // 896 + 9*192
#define NS_ALL 41
#define NS_X   14

// -------- device scratch (allocation-free rule) -----------------------------
__device__ __half g_xs[(size_t)8 * 16 * 4096 * 96];      // 100.7 MB
__device__ __half g_hs[2][(size_t)kNPix * 192];          // 2 x 12.6 MB
__device__ float  g_c [(size_t)kNPix * 64];              // 8.4 MB
__device__ __half g_Wb[(size_t)256 * KALL2];             // 1.35 MB
__device__ __align__(16) __half g_zeros[8];              // stays zero

// -------- helpers -----------------------------------------------------------
__device__ __forceinline__ uint32_t sm_u32(const void* p) {
    return (uint32_t)__cvta_generic_to_shared(p);
}
__device__ __forceinline__ uint32_t swz(uint32_t o) { return o ^ ((o >> 3) & 0x70); }

__device__ __forceinline__ void cp16(uint32_t dst, const void* src) {
    asm volatile("cp.async.cg.shared.global [%0], [%1], 16;"
                 :: "r"(dst), "l"(src));
}
__device__ __forceinline__ void cp_commit() {
    asm volatile("cp.async.commit_group;" ::: "memory");
}
__device__ __forceinline__ void cp_wait0() {
    asm volatile("cp.async.wait_group 0;" ::: "memory");
}
__device__ __forceinline__ void cp_wait1() {
    asm volatile("cp.async.wait_group 1;" ::: "memory");
}
__device__ __forceinline__ void ldsm4(uint32_t* r, uint32_t a) {
    asm volatile("ldmatrix.sync.aligned.m8n8.x4.shared.b16 {%0,%1,%2,%3}, [%4];"
                 : "=r"(r[0]), "=r"(r[1]), "=r"(r[2]), "=r"(r[3]) : "r"(a));
}
__device__ __forceinline__ void mma16816(float* c, const uint32_t* a,
                                         const uint32_t* b) {
    asm volatile(
        "mma.sync.aligned.m16n8k16.row.col.f32.f16.f16.f32 "
        "{%0,%1,%2,%3}, {%4,%5,%6,%7}, {%8,%9}, {%0,%1,%2,%3};"
        : "+f"(c[0]), "+f"(c[1]), "+f"(c[2]), "+f"(c[3])
        : "r"(a[0]), "r"(a[1]), "r"(a[2]), "r"(a[3]), "r"(b[0]), "r"(b[1]));
}
__device__ __forceinline__ float hsig(float v) {
    return fminf(fmaxf(v + 3.f, 0.f), 6.f) * (1.f / 6.f);
}

// -------- precompute: B' weights in interleaved K order ----------------------
__global__ void wb_kernel(const float* __restrict__ W, const float* __restrict__ U)
{
    int k_all = blockIdx.x;      // 0..KALL2-1
    int n = threadIdx.x;         // 0..255
    float v = 0.f;
    int sub = 0;
    bool valid = false;
    if (k_all < KX2) {
        if (k_all < 864) {
            int tap = k_all / 96, r = k_all % 96;
            sub = r / 32;
            int cin = r % 32;
            v = W[(size_t)(tap * 32 + cin) * 256 + n];
            valid = true;
        }
    } else {
        int k = k_all - KX2;
        int tap = k / 192, r = k % 192;
        sub = r / 64;
        int cin = r % 64;
        v = U[(size_t)(tap * 64 + cin) * 256 + n];
        valid = true;
    }
    __half o = __float2half(0.f);
    if (valid) {
        __half hi = __float2half(v);
        o = (sub == 1) ? __float2half(v - __half2float(hi)) : hi;
    }
    g_Wb[(size_t)n * KALL2 + k_all] = o;
}

// -------- precompute: x split image ------------------------------------------
__global__ void xs_kernel(const float* __restrict__ x)
{
    size_t i = (size_t)blockIdx.x * blockDim.x + threadIdx.x;  // 16.7M
    int cin = (int)(i & 31);
    size_t p = i >> 5;
    float v = x[i];
    __half hi = __float2half(v);
    __half lo = __float2half(v - __half2float(hi));
    g_xs[p * 96 + cin]      = hi;
    g_xs[p * 96 + 32 + cin] = hi;
    g_xs[p * 96 + 64 + cin] = lo;
}

// -------- main step kernel ---------------------------------------------------
// 256 CTAs x 512 threads; CTA = 128 pixels x 256 gates; 16 warps = 4(M)x4(N),
// warp tile 32x64. Kc=64. 3-stage ring: A[3] 16KB @0/16K/32K,
// B[3] 32KB @48K/80K/112K  -> 144KB dynamic smem.

__global__ __launch_bounds__(512, 1)
void lstm_step_kernel(const float* __restrict__ bias, float* __restrict__ out,
                      int t, int last)
{
    extern __shared__ __align__(16) char dsm_raw[];
    __shared__ float s_bias[256];

    const int tid = threadIdx.x;
    const int wid = tid >> 5;
    const int lane = tid & 31;
    const int m_tile = blockIdx.x * 128;

    const uint32_t dyn = sm_u32(dsm_raw);
    const uint32_t base = (dyn + 1023) & ~1023u;
    char* dptr = dsm_raw + (base - dyn);

    if (tid < 64) ((float4*)s_bias)[tid] = ((const float4*)bias)[tid];

    const int NS = (t == 0) ? NS_X : NS_ALL;
    const __half* h_rd = g_hs[t & 1];          // h_{t-1}
    __half*       h_wr = g_hs[(t & 1) ^ 1];    // h_t

    auto load_slab = [&](int s, int buf) {
        const uint32_t abuf = base + (uint32_t)buf * 16384;
        const uint32_t bbuf = base + 49152 + (uint32_t)buf * 32768;
        // A: 1024 16B chunks (128 rows x 8 kgroups), 2 per thread
#pragma unroll
        for (int i = 0; i < 2; i++) {
            int c = tid + i * 512;
            int m = c >> 3, kg = c & 7;
            int k0 = s * 64 + kg * 8;
            int p = m_tile + m;
            int bb = p >> 12, rem = p & 4095, py = rem >> 6, px = rem & 63;
            const __half* src = g_zeros;
            if (k0 < KX2) {
                if (k0 < 864) {
                    int tap = k0 / 96, ch = k0 % 96;   // ch multiple of 8
                    int y = py + tap / 3 - 1, xw = px + tap % 3 - 1;
                    if ((unsigned)y < 64u && (unsigned)xw < 64u)
                        src = g_xs + ((size_t)((bb * 16 + t) * 4096
                                               + (y << 6) + xw)) * 96 + ch;
                }
            } else {
                int k = k0 - KX2;
                int tap = k / 192, ch = k % 192;        // ch multiple of 8
                int y = py + tap / 3 - 1, xw = px + tap % 3 - 1;
                if ((unsigned)y < 64u && (unsigned)xw < 64u)
                    src = h_rd + ((size_t)((bb << 12) + (y << 6) + xw)) * 192 + ch;
            }
            cp16(abuf + swz((uint32_t)(m * 128 + kg * 16)), src);
        }
        // B: 2048 16B chunks (256 rows x 8 kgroups), 4 per thread
#pragma unroll
        for (int i = 0; i < 4; i++) {
            int c = tid + i * 512;
            int n = c >> 3, kg = c & 7;
            cp16(bbuf + swz((uint32_t)(n * 128 + kg * 16)),
                 g_Wb + (size_t)n * KALL2 + s * 64 + kg * 8);
        }
    };

    // accumulators: 2 m-subtiles x 8 n-subtiles x 4 f32
    float cfr[2][8][4];
#pragma unroll
    for (int i = 0; i < 2; i++)
#pragma unroll
        for (int j = 0; j < 8; j++)
#pragma unroll
            for (int q = 0; q < 4; q++) cfr[i][j][q] = 0.f;

    const int wm0 = (wid >> 2) * 32;
    const int wn0 = (wid & 3) * 64;

    // 3-stage ring preamble: slabs 0 and 1 in flight
    load_slab(0, 0);
    cp_commit();
    load_slab(1, 1);
    cp_commit();

    int buf = 0;               // buffer of slab s
    for (int s = 0; s < NS; s++) {
        // slab s must be complete; slab s+1 may remain in flight
        if (s == NS - 1) cp_wait0(); else cp_wait1();
        __syncthreads();
        // refill the buffer freed by slab s-1 (all warps are past its compute)
        if (s + 2 < NS) {
            int nb = buf - 1; if (nb < 0) nb += 3;   // (s+2)%3
            load_slab(s + 2, nb);
            cp_commit();
        }

        const uint32_t abuf = base + (uint32_t)buf * 16384;
        const uint32_t bbuf = base + 49152 + (uint32_t)buf * 32768;
        const uint32_t arow = (uint32_t)(wm0 + (lane & 7) + ((lane >> 3) & 1) * 8);
        const uint32_t brow = (uint32_t)(wn0 + (lane & 7) + (lane >> 4) * 8);
#pragma unroll
        for (int ks = 0; ks < 4; ks++) {
            const uint32_t acol = (uint32_t)(ks * 16 + (lane >> 4) * 8) * 2;
            const uint32_t bcol = (uint32_t)(ks * 16 + ((lane >> 3) & 1) * 8) * 2;
            uint32_t a0[4], a1[4];
            ldsm4(a0, abuf + swz(arow * 128 + acol));
            ldsm4(a1, abuf + swz((arow + 16) * 128 + acol));
#pragma unroll
            for (int p = 0; p < 4; p++) {
                uint32_t b[4];
                ldsm4(b, bbuf + swz((brow + p * 16) * 128 + bcol));
                mma16816(cfr[0][2 * p],     a0, b);
                mma16816(cfr[0][2 * p + 1], a0, b + 2);
                mma16816(cfr[1][2 * p],     a1, b);
                mma16816(cfr[1][2 * p + 1], a1, b + 2);
            }
        }
        if (++buf == 3) buf = 0;
    }
    __syncthreads();   // all mma done; smem buffers free for staging

    // ---- fused LSTM epilogue: two rounds of 64 pixels x 256 gates ----------
    float* zbuf = (float*)dptr;                 // 64*256 f32 = 64KB

    for (int r = 0; r < 2; r++) {
        if ((wm0 >> 6) == r) {
#pragma unroll
            for (int mi = 0; mi < 2; mi++) {
                int ml = (wm0 & 63) + mi * 16 + (lane >> 2);
#pragma unroll
                for (int nj = 0; nj < 8; nj++) {
                    int n = wn0 + nj * 8 + 2 * (lane & 3);
                    *(float2*)(zbuf + ml * 256 + n) =
                        make_float2(cfr[mi][nj][0], cfr[mi][nj][1]);
                    *(float2*)(zbuf + (ml + 8) * 256 + n) =
                        make_float2(cfr[mi][nj][2], cfr[mi][nj][3]);
                }
            }
        }
        __syncthreads();

        {   // gates: 64 pixels x 64 f; thread -> pixel p, 8 f values
            const int p = tid >> 3;
            const int f0 = (tid & 7) * 8;
            const int pix = m_tile + r * 64 + p;
            const float* zr = zbuf + p * 256;
            float cp8[8] = {0.f, 0.f, 0.f, 0.f, 0.f, 0.f, 0.f, 0.f};
            if (t > 0) {
                float4 c0 = *(const float4*)(g_c + (size_t)pix * 64 + f0);
                float4 c1 = *(const float4*)(g_c + (size_t)pix * 64 + f0 + 4);
                cp8[0] = c0.x; cp8[1] = c0.y; cp8[2] = c0.z; cp8[3] = c0.w;
                cp8[4] = c1.x; cp8[5] = c1.y; cp8[6] = c1.z; cp8[7] = c1.w;
            }
            float cn8[8], hn8[8];
#pragma unroll
            for (int j = 0; j < 8; j++) {
                int f = f0 + j;
                float vi = zr[f]       + s_bias[f];
                float vf = zr[64 + f]  + s_bias[64 + f];
                float vc = zr[128 + f] + s_bias[128 + f];
                float vo = zr[192 + f] + s_bias[192 + f];
                float cn = hsig(vf) * cp8[j] + hsig(vi) * fmaxf(vc, 0.f);
                cn8[j] = cn;
                hn8[j] = hsig(vo) * fmaxf(cn, 0.f);
            }
            if (last) {
                *(float4*)(out + (size_t)pix * 64 + f0) =
                    make_float4(hn8[0], hn8[1], hn8[2], hn8[3]);
                *(float4*)(out + (size_t)pix * 64 + f0 + 4) =
                    make_float4(hn8[4], hn8[5], hn8[6], hn8[7]);
            } else {
                *(float4*)(g_c + (size_t)pix * 64 + f0) =
                    make_float4(cn8[0], cn8[1], cn8[2], cn8[3]);
                *(float4*)(g_c + (size_t)pix * 64 + f0 + 4) =
                    make_float4(cn8[4], cn8[5], cn8[6], cn8[7]);
                // pack hi/lo splits in registers
                uint32_t ph[4], pl[4];
#pragma unroll
                for (int j2 = 0; j2 < 4; j2++) {
                    __half h0 = __float2half(hn8[2 * j2]);
                    __half h1 = __float2half(hn8[2 * j2 + 1]);
                    __half l0 = __float2half(hn8[2 * j2]     - __half2float(h0));
                    __half l1 = __float2half(hn8[2 * j2 + 1] - __half2float(h1));
                    ph[j2] = (uint32_t)__half_as_ushort(h0)
                           | ((uint32_t)__half_as_ushort(h1) << 16);
                    pl[j2] = (uint32_t)__half_as_ushort(l0)
                           | ((uint32_t)__half_as_ushort(l1) << 16);
                }
                uint4 vh = make_uint4(ph[0], ph[1], ph[2], ph[3]);
                uint4 vl = make_uint4(pl[0], pl[1], pl[2], pl[3]);
                *(uint4*)(h_wr + (size_t)pix * 192 + f0)       = vh;
                *(uint4*)(h_wr + (size_t)pix * 192 + 64 + f0)  = vh;
                *(uint4*)(h_wr + (size_t)pix * 192 + 128 + f0) = vl;
            }
        }
        __syncthreads();
    }
}

// ---------------------------------------------------------------------------

extern "C" void kernel_launch(void* const* d_in, const int* in_sizes, int n_in,
                              void* d_out, int out_size)
{
    const float* x    = (const float*)d_in[0];   // (8,16,64,64,32)
    const float* Wp   = (const float*)d_in[1];   // (3,3,32,256)
    const float* Up   = (const float*)d_in[2];   // (3,3,64,256)
    const float* bias = (const float*)d_in[3];   // (256,)
    float* out = (float*)d_out;                  // (8,64,64,64)

    cudaFuncSetAttribute(lstm_step_kernel,
                         cudaFuncAttributeMaxDynamicSharedMemorySize, 148480);

    wb_kernel<<<KALL2, 256>>>(Wp, Up);
    xs_kernel<<<65536, 256>>>(x);

    for (int t = 0; t < kT; t++)
        lstm_step_kernel<<<256, 512, 148480>>>(bias, out, t, t == kT - 1 ? 1 : 0);
}